// round 6
// baseline (speedup 1.0000x reference)
#include <cuda_runtime.h>

// ---------------------------------------------------------------------------
// ECLoss with spatial pruning.
// exp(-|q-d|^2 / (2*0.3^2)) at distance 2.0 is 2.3e-10 -> truncate at R=2.
// Data grid-sorted row-major (44x44 cells, h=0.25 over [-5.5,5.5]^2);
// queries Morton-sorted per bin so each warp covers a compact blob.
// Warp-autonomous main loop: bbox -> per-row ellipse-trimmed contiguous
// point ranges -> broadcast loads, 4 fma-pipe + 1 MUFU per pair.
// Dynamic chunk stealing balances the center-heavy work.
// ---------------------------------------------------------------------------

namespace {
constexpr int NTR    = 20000;
constexpr int NTE    = 10000;
constexpr int NBATCH = 1024;
constexpr int NQ     = 10000;
constexpr int NBINS  = 15;
constexpr int NCLS   = 10;
constexpr int NQTOT  = NBINS * NQ;          // 150000

constexpr int GW = 44, GH = 44;             // data grid
constexpr int NCELLS = GW * GH;             // 1936
constexpr int MGRID  = 4096;                // 64x64 Morton space (queries)
constexpr int QBUCKETS = NBINS * MGRID;     // 61440

constexpr float XMIN = -5.5f;
constexpr float H    = 0.25f;
constexpr float INVH = 4.0f;
constexpr float RCUT = 2.0f;
constexpr float R2   = RCUT * RCUT;

constexpr int WPB     = 313;                // warp-chunks per bin (ceil 10000/32)
constexpr int NCHUNK  = NBINS * WPB;        // 4695
constexpr int THREADS = 128;
constexpr int MAINBLK = 592;                // ~4 blocks/SM, stealing balances

constexpr double BW_D   = 0.3;
constexpr double PI_D   = 3.14159265358979323846;
constexpr double L2E_D  = 1.4426950408889634073599246810019;
constexpr double KDEN_D = 2.0 * PI_D * BW_D * BW_D;

constexpr float C1 = (float)(L2E_D / (BW_D * BW_D));
constexpr float C2 = (float)(L2E_D / (2.0 * BW_D * BW_D));
constexpr float KDEN_F = (float)KDEN_D;
constexpr float DEN_TR = (float)((double)NTR * KDEN_D);
constexpr float DEN_TE = (float)((double)NTE * KDEN_D);
constexpr float L2E_F  = (float)L2E_D;
constexpr float BIN_STEP = 1.0f / 15.0f;
}

// ------------------------- device globals ----------------------------------
__device__ float4 g_str[NTR];        // sorted transformed train
__device__ float4 g_ste[NTE];        // sorted transformed test
__device__ float4 g_sbw[NBATCH];     // sorted transformed batch (weighted)
__device__ float4 g_q[NQTOT];        // sorted queries (qx, qy, qc, -)

__device__ int g_qcnt[QBUCKETS];
__device__ int g_qoff[QBUCKETS + 1];
__device__ int g_qcur[QBUCKETS];
__device__ int g_trcnt[NCELLS], g_troff[NCELLS + 1], g_trcur[NCELLS];
__device__ int g_tecnt[NCELLS], g_teoff[NCELLS + 1], g_tecur[NCELLS];
__device__ int g_bwcnt[NCELLS], g_bwoff[NCELLS + 1], g_bwcur[NCELLS];

__device__ int   g_hist_tr[NBINS];
__device__ int   g_hist_te[NBINS];
__device__ int   g_cnt;
__device__ int   g_work;
__device__ float g_contrib[NQTOT];

// ------------------------- helpers -----------------------------------------
__device__ __forceinline__ float ex2(float x) {
    float r;
    asm("ex2.approx.ftz.f32 %0, %1;" : "=f"(r) : "f"(x));
    return r;
}
__device__ __forceinline__ float bin_lo(int k) { return (float)k * BIN_STEP; }
__device__ __forceinline__ float bin_hi(int k) {
    return (k == NBINS - 1) ? 1.0f : (float)(k + 1) * BIN_STEP;
}
__device__ __forceinline__ int cell_coord(float v) {
    int c = (int)floorf((v - XMIN) * INVH);
    return min(max(c, 0), GW - 1);
}
__device__ __forceinline__ unsigned morton(unsigned x, unsigned y) {
    unsigned r = 0;
    #pragma unroll
    for (int i = 0; i < 6; i++)
        r |= (((x >> i) & 1u) << (2 * i)) | (((y >> i) & 1u) << (2 * i + 1));
    return r;
}

// ------------------------- K1: init ----------------------------------------
__global__ void ec_init_kernel() {
    int i = blockIdx.x * blockDim.x + threadIdx.x;
    int stride = gridDim.x * blockDim.x;
    for (int k = i; k < QBUCKETS; k += stride) g_qcnt[k] = 0;
    for (int k = i; k < NCELLS; k += stride) {
        g_trcnt[k] = 0; g_tecnt[k] = 0; g_bwcnt[k] = 0;
    }
    if (i < NBINS) { g_hist_tr[i] = 0; g_hist_te[i] = 0; }
    if (i == 0) { g_cnt = 0; g_work = 0; }
}

// ------------------------- K2: count ---------------------------------------
__global__ void ec_count_kernel(const float* __restrict__ mc,
                                const float* __restrict__ train_x,
                                const float* __restrict__ test_x,
                                const float* __restrict__ batch_x,
                                const int*   __restrict__ by,
                                const int*   __restrict__ bp,
                                const float* __restrict__ trp,
                                const float* __restrict__ tep) {
    int i = blockIdx.x * blockDim.x + threadIdx.x;
    if (i < NQTOT) {
        float qx = mc[2 * i], qy = mc[2 * i + 1];
        int bin = i / NQ;
        unsigned m = morton((unsigned)cell_coord(qx), (unsigned)cell_coord(qy));
        atomicAdd(&g_qcnt[bin * MGRID + m], 1);
        return;
    }
    int j = i - NQTOT;
    if (j < NTR) {
        float x = train_x[2 * j], y = train_x[2 * j + 1];
        atomicAdd(&g_trcnt[cell_coord(y) * GW + cell_coord(x)], 1);
        float p = trp[j];
        #pragma unroll
        for (int k = 0; k < NBINS; k++)
            if (p > bin_lo(k) && p <= bin_hi(k)) { atomicAdd(&g_hist_tr[k], 1); break; }
        return;
    }
    j -= NTR;
    if (j < NTE) {
        float x = test_x[2 * j], y = test_x[2 * j + 1];
        atomicAdd(&g_tecnt[cell_coord(y) * GW + cell_coord(x)], 1);
        float p = tep[j];
        #pragma unroll
        for (int k = 0; k < NBINS; k++)
            if (p > bin_lo(k) && p <= bin_hi(k)) { atomicAdd(&g_hist_te[k], 1); break; }
        return;
    }
    j -= NTE;
    if (j < NBATCH) {
        float x = batch_x[2 * j], y = batch_x[2 * j + 1];
        atomicAdd(&g_bwcnt[cell_coord(y) * GW + cell_coord(x)], 1);
        if (by[j] == bp[j]) atomicAdd(&g_cnt, 1);
    }
}

// ------------------------- K3: scans ---------------------------------------
__device__ void scan_excl(const int* cnt, int* off, int* cur, int n) {
    __shared__ int sh[1024];
    int t = threadIdx.x;
    int chunk = (n + 1023) / 1024;
    int lo = t * chunk, hi = min(lo + chunk, n);
    int s = 0;
    for (int i = lo; i < hi; i++) s += cnt[i];
    sh[t] = s;
    __syncthreads();
    for (int d = 1; d < 1024; d <<= 1) {
        int v = (t >= d) ? sh[t - d] : 0;
        __syncthreads();
        sh[t] += v;
        __syncthreads();
    }
    int excl = (t == 0) ? 0 : sh[t - 1];
    for (int i = lo; i < hi; i++) {
        off[i] = excl; cur[i] = excl;
        excl += cnt[i];
    }
    if (hi == n && lo <= n) off[n] = excl;
    if (n == 0 && t == 0) off[0] = 0;
    __syncthreads();
}

__global__ void ec_scan_kernel() {
    scan_excl(g_qcnt,  g_qoff,  g_qcur,  QBUCKETS);
    scan_excl(g_trcnt, g_troff, g_trcur, NCELLS);
    scan_excl(g_tecnt, g_teoff, g_tecur, NCELLS);
    scan_excl(g_bwcnt, g_bwoff, g_bwcur, NCELLS);
}

// ------------------------- K4: scatter -------------------------------------
__global__ void ec_scatter_kernel(const float* __restrict__ mc,
                                  const float* __restrict__ train_x,
                                  const float* __restrict__ test_x,
                                  const float* __restrict__ batch_x,
                                  const int*   __restrict__ by,
                                  const int*   __restrict__ bp) {
    int i = blockIdx.x * blockDim.x + threadIdx.x;
    if (i < NQTOT) {
        float qx = mc[2 * i], qy = mc[2 * i + 1];
        int bin = i / NQ;
        unsigned m = morton((unsigned)cell_coord(qx), (unsigned)cell_coord(qy));
        int pos = atomicAdd(&g_qcur[bin * MGRID + m], 1);
        g_q[pos] = make_float4(qx, qy, -(qx * qx + qy * qy) * C2, 0.0f);
        return;
    }
    int j = i - NQTOT;
    if (j < NTR) {
        float x = train_x[2 * j], y = train_x[2 * j + 1];
        int pos = atomicAdd(&g_trcur[cell_coord(y) * GW + cell_coord(x)], 1);
        g_str[pos] = make_float4(x * C1, y * C1, -(x * x + y * y) * C2, 0.0f);
        return;
    }
    j -= NTR;
    if (j < NTE) {
        float x = test_x[2 * j], y = test_x[2 * j + 1];
        int pos = atomicAdd(&g_tecur[cell_coord(y) * GW + cell_coord(x)], 1);
        g_ste[pos] = make_float4(x * C1, y * C1, -(x * x + y * y) * C2, 0.0f);
        return;
    }
    j -= NTE;
    if (j < NBATCH) {
        float x = batch_x[2 * j], y = batch_x[2 * j + 1];
        bool c = (by[j] == bp[j]);
        int pos = atomicAdd(&g_bwcur[cell_coord(y) * GW + cell_coord(x)], 1);
        g_sbw[pos] = make_float4(x * C1, y * C1,
                                 c ? -(x * x + y * y) * C2 : -1e30f, 0.0f);
    }
}

// ------------------------- K5: main ----------------------------------------
__device__ __forceinline__ float range_sum(const float4* __restrict__ d,
                                           int s, int e,
                                           float qx, float qy, float qc,
                                           float& a0, float& a1,
                                           float& a2, float& a3) {
    int i = s;
    for (; i + 4 <= e; i += 4) {
        float4 p0 = __ldg(d + i + 0);
        float4 p1 = __ldg(d + i + 1);
        float4 p2 = __ldg(d + i + 2);
        float4 p3 = __ldg(d + i + 3);
        a0 += ex2(fmaf(p0.x, qx, fmaf(p0.y, qy, p0.z) + qc));
        a1 += ex2(fmaf(p1.x, qx, fmaf(p1.y, qy, p1.z) + qc));
        a2 += ex2(fmaf(p2.x, qx, fmaf(p2.y, qy, p2.z) + qc));
        a3 += ex2(fmaf(p3.x, qx, fmaf(p3.y, qy, p3.z) + qc));
    }
    for (; i < e; i++) {
        float4 p = __ldg(d + i);
        a0 += ex2(fmaf(p.x, qx, fmaf(p.y, qy, p.z) + qc));
    }
    return 0.0f;
}

__global__ void __launch_bounds__(THREADS)
ec_main_kernel(const float* __restrict__ W, const float* __restrict__ b) {
    const int lane = threadIdx.x & 31;
    const unsigned FULL = 0xffffffffu;

    while (true) {
        int c = 0;
        if (lane == 0) c = atomicAdd(&g_work, 1);
        c = __shfl_sync(FULL, c, 0);
        if (c >= NCHUNK) break;

        int bin = c / WPB;
        int lw  = c - bin * WPB;
        int qi  = lw * 32 + lane;
        bool act = (qi < NQ);
        int slot = bin * NQ + (act ? qi : NQ - 1);

        float4 qp = g_q[slot];
        float qx = qp.x, qy = qp.y, qc = qp.z;

        // warp bbox
        float bx0 = qx, bx1 = qx, by0 = qy, by1 = qy;
        #pragma unroll
        for (int o = 16; o; o >>= 1) {
            bx0 = fminf(bx0, __shfl_xor_sync(FULL, bx0, o));
            bx1 = fmaxf(bx1, __shfl_xor_sync(FULL, bx1, o));
            by0 = fminf(by0, __shfl_xor_sync(FULL, by0, o));
            by1 = fmaxf(by1, __shfl_xor_sync(FULL, by1, o));
        }

        int r0 = max(0,      (int)floorf((by0 - RCUT - XMIN) * INVH));
        int r1 = min(GH - 1, (int)floorf((by1 + RCUT - XMIN) * INVH));

        float t0 = 0.f, t1 = 0.f, t2a = 0.f, t3 = 0.f;
        float e0 = 0.f, e1 = 0.f, e2 = 0.f, e3 = 0.f;
        float w0 = 0.f, w1 = 0.f, w2 = 0.f, w3 = 0.f;

        for (int r = r0; r <= r1; r++) {
            float rl = XMIN + (float)r * H;
            float rh = rl + H;
            float dy = fmaxf(fmaxf(by0 - rh, rl - by1), 0.0f);
            float rem = R2 - dy * dy;
            if (rem <= 0.0f) continue;
            float xr = sqrtf(rem);
            int c0 = max(0,      (int)floorf((bx0 - xr - XMIN) * INVH));
            int c1 = min(GW - 1, (int)floorf((bx1 + xr - XMIN) * INVH));
            int base = r * GW;
            range_sum(g_str, g_troff[base + c0], g_troff[base + c1 + 1],
                      qx, qy, qc, t0, t1, t2a, t3);
            range_sum(g_ste, g_teoff[base + c0], g_teoff[base + c1 + 1],
                      qx, qy, qc, e0, e1, e2, e3);
            range_sum(g_sbw, g_bwoff[base + c0], g_bwoff[base + c1 + 1],
                      qx, qy, qc, w0, w1, w2, w3);
        }
        float s_tr = (t0 + t1) + (t2a + t3);
        float s_te = (e0 + e1) + (e2 + e3);
        float s_w  = (w0 + w1) + (w2 + w3);

        // ---- per-query epilogue ----
        float cnt    = (float)g_cnt;
        float p_y    = cnt * (1.0f / 1024.0f);
        float kde_tr = s_tr / DEN_TR;
        float kde_te = s_te / DEN_TE;
        float kde_w  = s_w / (fmaxf(cnt, 1.0f) * KDEN_F);

        float tr_rate = (float)g_hist_tr[bin] / 20000.0f;
        float te_rate = (float)g_hist_te[bin] / 10000.0f;

        float l[NCLS];
        float lmax = -1e30f;
        #pragma unroll
        for (int k = 0; k < NCLS; k++) {
            l[k] = fmaf(qx, __ldg(W + k), fmaf(qy, __ldg(W + NCLS + k), __ldg(b + k)));
            lmax = fmaxf(lmax, l[k]);
        }
        float se = 0.0f;
        #pragma unroll
        for (int k = 0; k < NCLS; k++) se += ex2((l[k] - lmax) * L2E_F);
        float hat_s = 1.0f / se;

        float lo = bin_lo(bin), hi = bin_hi(bin);
        float idx = (hat_s >= lo && hat_s <= hi) ? 1.0f : 0.0f;

        float d_t = (te_rate > 0.0f) ? kde_te / te_rate : 0.0f;
        float d_s = (tr_rate > 0.0f) ? kde_tr / tr_rate : 0.0f;

        float p_hs = kde_w * p_y / (kde_tr + 1e-8f);
        p_hs = fminf(fmaxf(p_hs, 0.0f), 1.0f);

        if (act) g_contrib[bin * NQ + qi] = p_hs * (d_t - d_s) * idx;
    }
}

// ------------------------- K6: final ---------------------------------------
__global__ void ec_final_kernel(float* __restrict__ out) {
    __shared__ float red[1024];
    int t = threadIdx.x;
    float ec = 0.0f;
    for (int bin = 0; bin < NBINS; bin++) {
        float s = 0.0f;
        for (int i = t; i < NQ; i += 1024) s += g_contrib[bin * NQ + i];
        red[t] = s;
        __syncthreads();
        for (int d = 512; d > 0; d >>= 1) {
            if (t < d) red[t] += red[t + d];
            __syncthreads();
        }
        if (t == 0) {
            float integral = (red[0] / (float)NQ) * 100.0f;
            float te_rate  = (float)g_hist_te[bin] / 10000.0f;
            if (te_rate > 0.0f) ec += te_rate * fabsf(integral);
        }
        __syncthreads();
    }
    if (t == 0) out[0] = ec;
}

// ------------------------- launch ------------------------------------------
extern "C" void kernel_launch(void* const* d_in, const int* in_sizes, int n_in,
                              void* d_out, int out_size) {
    const float* batch_x = (const float*)d_in[0];
    const int*   by      = (const int*)  d_in[1];
    const int*   bp      = (const int*)  d_in[2];
    const float* trp     = (const float*)d_in[3];
    const float* tep     = (const float*)d_in[4];

    const float *train_x, *test_x, *W, *b, *mc;
    if (in_sizes[5] == NTR * 2) {
        train_x = (const float*)d_in[5];
        test_x  = (const float*)d_in[6];
        W       = (const float*)d_in[7];
        b       = (const float*)d_in[8];
        mc      = (const float*)d_in[9];
    } else {
        W       = (const float*)d_in[5];
        b       = (const float*)d_in[6];
        train_x = (const float*)d_in[7];
        test_x  = (const float*)d_in[8];
        mc      = (const float*)d_in[9];
    }

    ec_init_kernel<<<64, 1024>>>();

    int total = NQTOT + NTR + NTE + NBATCH;
    ec_count_kernel<<<(total + 255) / 256, 256>>>(mc, train_x, test_x, batch_x,
                                                  by, bp, trp, tep);
    ec_scan_kernel<<<1, 1024>>>();
    ec_scatter_kernel<<<(total + 255) / 256, 256>>>(mc, train_x, test_x, batch_x,
                                                    by, bp);
    ec_main_kernel<<<MAINBLK, THREADS>>>(W, b);
    ec_final_kernel<<<1, 1024>>>((float*)d_out);
}

// round 7
// speedup vs baseline: 2.2084x; 2.2084x over previous
#include <cuda_runtime.h>

// ---------------------------------------------------------------------------
// ECLoss, spatially pruned KDE (R=1.8 cutoff; dropped kernel <= 1.5e-8).
// Queries sorted by (1.0-unit major cell row-major, 0.25 minor) -> each
// 32-query warp chunk is a compact blob. Data grid-sorted row-major in
// 0.25 cells. One 4-warp block per chunk: warps split grid rows (stride 4),
// per-row ellipse-trimmed contiguous ranges, 8-deep unrolled broadcast
// loads (MLP 8), deterministic shared combine. Dynamic block-level stealing.
// ---------------------------------------------------------------------------

namespace {
constexpr int NTR    = 20000;
constexpr int NTE    = 10000;
constexpr int NBATCH = 1024;
constexpr int NQ     = 10000;
constexpr int NBINS  = 15;
constexpr int NCLS   = 10;
constexpr int NQTOT  = NBINS * NQ;          // 150000

constexpr int GW = 44, GH = 44;             // data grid (0.25 cells, [-5.5,5.5])
constexpr int NCELLS = GW * GH;             // 1936
constexpr int QCELLS = 1600;                // 10x10 major x 4x4 minor
constexpr int QBUCKETS = NBINS * QCELLS;    // 24000

constexpr float XMIN = -5.5f;
constexpr float H    = 0.25f;
constexpr float INVH = 4.0f;
constexpr float RCUT = 1.8f;
constexpr float R2   = RCUT * RCUT;

constexpr int WPB     = 313;                // 32-query chunks per bin
constexpr int NCHUNK  = NBINS * WPB;        // 4695
constexpr int THREADS = 128;                // 4 warps per block
constexpr int MAINBLK = 592;

constexpr double BW_D   = 0.3;
constexpr double PI_D   = 3.14159265358979323846;
constexpr double L2E_D  = 1.4426950408889634073599246810019;
constexpr double KDEN_D = 2.0 * PI_D * BW_D * BW_D;

constexpr float C1 = (float)(L2E_D / (BW_D * BW_D));
constexpr float C2 = (float)(L2E_D / (2.0 * BW_D * BW_D));
constexpr float KDEN_F = (float)KDEN_D;
constexpr float DEN_TR = (float)((double)NTR * KDEN_D);
constexpr float DEN_TE = (float)((double)NTE * KDEN_D);
constexpr float L2E_F  = (float)L2E_D;
constexpr float BIN_STEP = 1.0f / 15.0f;
}

// ------------------------- device globals ----------------------------------
__device__ float4 g_str[NTR];
__device__ float4 g_ste[NTE];
__device__ float4 g_sbw[NBATCH];
__device__ float4 g_q[NQTOT];               // (qx, qy, qc, -)

__device__ int g_qcnt[QBUCKETS];
__device__ int g_qoff[QBUCKETS + 1];
__device__ int g_qcur[QBUCKETS];
__device__ int g_trcnt[NCELLS], g_troff[NCELLS + 1], g_trcur[NCELLS];
__device__ int g_tecnt[NCELLS], g_teoff[NCELLS + 1], g_tecur[NCELLS];
__device__ int g_bwcnt[NCELLS], g_bwoff[NCELLS + 1], g_bwcur[NCELLS];

__device__ int   g_hist_tr[NBINS];
__device__ int   g_hist_te[NBINS];
__device__ int   g_cnt;
__device__ int   g_work;
__device__ float g_contrib[NQTOT];

// ------------------------- helpers -----------------------------------------
__device__ __forceinline__ float ex2(float x) {
    float r;
    asm("ex2.approx.ftz.f32 %0, %1;" : "=f"(r) : "f"(x));
    return r;
}
__device__ __forceinline__ float bin_lo(int k) { return (float)k * BIN_STEP; }
__device__ __forceinline__ float bin_hi(int k) {
    return (k == NBINS - 1) ? 1.0f : (float)(k + 1) * BIN_STEP;
}
__device__ __forceinline__ int cell_coord(float v) {
    int c = (int)floorf((v - XMIN) * INVH);
    return min(max(c, 0), GW - 1);
}
// Hierarchical query key: major 1.0-cell row-major, 0.25 minor row-major.
__device__ __forceinline__ int qkey(float x, float y) {
    int tx = min(max((int)floorf((x + 5.0f) * 4.0f), 0), 39);
    int ty = min(max((int)floorf((y + 5.0f) * 4.0f), 0), 39);
    int mx = tx >> 2, my = ty >> 2;
    int sx = tx & 3,  sy = ty & 3;
    return (my * 10 + mx) * 16 + (sy * 4 + sx);
}

// ------------------------- K1: init ----------------------------------------
__global__ void ec_init_kernel() {
    int i = blockIdx.x * blockDim.x + threadIdx.x;
    int stride = gridDim.x * blockDim.x;
    for (int k = i; k < QBUCKETS; k += stride) g_qcnt[k] = 0;
    for (int k = i; k < NCELLS; k += stride) {
        g_trcnt[k] = 0; g_tecnt[k] = 0; g_bwcnt[k] = 0;
    }
    if (i < NBINS) { g_hist_tr[i] = 0; g_hist_te[i] = 0; }
    if (i == 0) { g_cnt = 0; g_work = 0; }
}

// ------------------------- K2: count ---------------------------------------
__global__ void ec_count_kernel(const float* __restrict__ mc,
                                const float* __restrict__ train_x,
                                const float* __restrict__ test_x,
                                const float* __restrict__ batch_x,
                                const int*   __restrict__ by,
                                const int*   __restrict__ bp,
                                const float* __restrict__ trp,
                                const float* __restrict__ tep) {
    int i = blockIdx.x * blockDim.x + threadIdx.x;
    if (i < NQTOT) {
        float qx = mc[2 * i], qy = mc[2 * i + 1];
        int bin = i / NQ;
        atomicAdd(&g_qcnt[bin * QCELLS + qkey(qx, qy)], 1);
        return;
    }
    int j = i - NQTOT;
    if (j < NTR) {
        float x = train_x[2 * j], y = train_x[2 * j + 1];
        atomicAdd(&g_trcnt[cell_coord(y) * GW + cell_coord(x)], 1);
        float p = trp[j];
        #pragma unroll
        for (int k = 0; k < NBINS; k++)
            if (p > bin_lo(k) && p <= bin_hi(k)) { atomicAdd(&g_hist_tr[k], 1); break; }
        return;
    }
    j -= NTR;
    if (j < NTE) {
        float x = test_x[2 * j], y = test_x[2 * j + 1];
        atomicAdd(&g_tecnt[cell_coord(y) * GW + cell_coord(x)], 1);
        float p = tep[j];
        #pragma unroll
        for (int k = 0; k < NBINS; k++)
            if (p > bin_lo(k) && p <= bin_hi(k)) { atomicAdd(&g_hist_te[k], 1); break; }
        return;
    }
    j -= NTE;
    if (j < NBATCH) {
        float x = batch_x[2 * j], y = batch_x[2 * j + 1];
        atomicAdd(&g_bwcnt[cell_coord(y) * GW + cell_coord(x)], 1);
        if (by[j] == bp[j]) atomicAdd(&g_cnt, 1);
    }
}

// ------------------------- K3: scans ---------------------------------------
__device__ void scan_excl(const int* cnt, int* off, int* cur, int n) {
    __shared__ int sh[1024];
    int t = threadIdx.x;
    int chunk = (n + 1023) / 1024;
    int lo = t * chunk, hi = min(lo + chunk, n);
    int s = 0;
    for (int i = lo; i < hi; i++) s += cnt[i];
    sh[t] = s;
    __syncthreads();
    for (int d = 1; d < 1024; d <<= 1) {
        int v = (t >= d) ? sh[t - d] : 0;
        __syncthreads();
        sh[t] += v;
        __syncthreads();
    }
    int excl = (t == 0) ? 0 : sh[t - 1];
    for (int i = lo; i < hi; i++) {
        off[i] = excl; cur[i] = excl;
        excl += cnt[i];
    }
    if (hi == n && lo <= n) off[n] = excl;
    __syncthreads();
}

__global__ void ec_scan_kernel() {
    scan_excl(g_qcnt,  g_qoff,  g_qcur,  QBUCKETS);
    scan_excl(g_trcnt, g_troff, g_trcur, NCELLS);
    scan_excl(g_tecnt, g_teoff, g_tecur, NCELLS);
    scan_excl(g_bwcnt, g_bwoff, g_bwcur, NCELLS);
}

// ------------------------- K4: scatter -------------------------------------
__global__ void ec_scatter_kernel(const float* __restrict__ mc,
                                  const float* __restrict__ train_x,
                                  const float* __restrict__ test_x,
                                  const float* __restrict__ batch_x,
                                  const int*   __restrict__ by,
                                  const int*   __restrict__ bp) {
    int i = blockIdx.x * blockDim.x + threadIdx.x;
    if (i < NQTOT) {
        float qx = mc[2 * i], qy = mc[2 * i + 1];
        int bin = i / NQ;
        int pos = atomicAdd(&g_qcur[bin * QCELLS + qkey(qx, qy)], 1);
        g_q[pos] = make_float4(qx, qy, -(qx * qx + qy * qy) * C2, 0.0f);
        return;
    }
    int j = i - NQTOT;
    if (j < NTR) {
        float x = train_x[2 * j], y = train_x[2 * j + 1];
        int pos = atomicAdd(&g_trcur[cell_coord(y) * GW + cell_coord(x)], 1);
        g_str[pos] = make_float4(x * C1, y * C1, -(x * x + y * y) * C2, 0.0f);
        return;
    }
    j -= NTR;
    if (j < NTE) {
        float x = test_x[2 * j], y = test_x[2 * j + 1];
        int pos = atomicAdd(&g_tecur[cell_coord(y) * GW + cell_coord(x)], 1);
        g_ste[pos] = make_float4(x * C1, y * C1, -(x * x + y * y) * C2, 0.0f);
        return;
    }
    j -= NTE;
    if (j < NBATCH) {
        float x = batch_x[2 * j], y = batch_x[2 * j + 1];
        bool c = (by[j] == bp[j]);
        int pos = atomicAdd(&g_bwcur[cell_coord(y) * GW + cell_coord(x)], 1);
        g_sbw[pos] = make_float4(x * C1, y * C1,
                                 c ? -(x * x + y * y) * C2 : -1e30f, 0.0f);
    }
}

// ------------------------- K5: main ----------------------------------------
__device__ __forceinline__ void range_sum(const float4* __restrict__ d,
                                          int s, int e,
                                          float qx, float qy, float qc,
                                          float& a0, float& a1,
                                          float& a2, float& a3) {
    int i = s;
    for (; i + 8 <= e; i += 8) {
        float4 p0 = __ldg(d + i + 0);
        float4 p1 = __ldg(d + i + 1);
        float4 p2 = __ldg(d + i + 2);
        float4 p3 = __ldg(d + i + 3);
        float4 p4 = __ldg(d + i + 4);
        float4 p5 = __ldg(d + i + 5);
        float4 p6 = __ldg(d + i + 6);
        float4 p7 = __ldg(d + i + 7);
        a0 += ex2(fmaf(p0.x, qx, fmaf(p0.y, qy, p0.z) + qc));
        a1 += ex2(fmaf(p1.x, qx, fmaf(p1.y, qy, p1.z) + qc));
        a2 += ex2(fmaf(p2.x, qx, fmaf(p2.y, qy, p2.z) + qc));
        a3 += ex2(fmaf(p3.x, qx, fmaf(p3.y, qy, p3.z) + qc));
        a0 += ex2(fmaf(p4.x, qx, fmaf(p4.y, qy, p4.z) + qc));
        a1 += ex2(fmaf(p5.x, qx, fmaf(p5.y, qy, p5.z) + qc));
        a2 += ex2(fmaf(p6.x, qx, fmaf(p6.y, qy, p6.z) + qc));
        a3 += ex2(fmaf(p7.x, qx, fmaf(p7.y, qy, p7.z) + qc));
    }
    for (; i < e; i++) {
        float4 p = __ldg(d + i);
        a0 += ex2(fmaf(p.x, qx, fmaf(p.y, qy, p.z) + qc));
    }
}

__global__ void __launch_bounds__(THREADS)
ec_main_kernel(const float* __restrict__ W, const float* __restrict__ b) {
    __shared__ float sh_tr[4][32], sh_te[4][32], sh_w[4][32];
    __shared__ int   sh_chunk;

    const int warp = threadIdx.x >> 5;
    const int lane = threadIdx.x & 31;
    const unsigned FULL = 0xffffffffu;

    while (true) {
        if (threadIdx.x == 0) sh_chunk = atomicAdd(&g_work, 1);
        __syncthreads();
        int c = sh_chunk;
        if (c >= NCHUNK) break;

        int bin = c / WPB;
        int lw  = c - bin * WPB;
        int qi  = lw * 32 + lane;
        bool act = (qi < NQ);
        int slot = bin * NQ + (act ? qi : NQ - 1);

        float4 qp = g_q[slot];
        float qx = qp.x, qy = qp.y, qc = qp.z;

        // warp bbox over the 32 queries (identical in every warp)
        float bx0 = qx, bx1 = qx, by0 = qy, by1 = qy;
        #pragma unroll
        for (int o = 16; o; o >>= 1) {
            bx0 = fminf(bx0, __shfl_xor_sync(FULL, bx0, o));
            bx1 = fmaxf(bx1, __shfl_xor_sync(FULL, bx1, o));
            by0 = fminf(by0, __shfl_xor_sync(FULL, by0, o));
            by1 = fmaxf(by1, __shfl_xor_sync(FULL, by1, o));
        }

        int r0 = max(0,      (int)floorf((by0 - RCUT - XMIN) * INVH));
        int r1 = min(GH - 1, (int)floorf((by1 + RCUT - XMIN) * INVH));

        float t0 = 0.f, t1 = 0.f, t2 = 0.f, t3 = 0.f;
        float e0 = 0.f, e1 = 0.f, e2 = 0.f, e3 = 0.f;
        float w0 = 0.f, w1 = 0.f, w2 = 0.f, w3 = 0.f;

        // warps split rows (stride 4) for fine-grained balance
        for (int r = r0 + warp; r <= r1; r += 4) {
            float rl = XMIN + (float)r * H;
            float rh = rl + H;
            float dy = fmaxf(fmaxf(by0 - rh, rl - by1), 0.0f);
            float rem = R2 - dy * dy;
            if (rem <= 0.0f) continue;
            float xr = sqrtf(rem);
            int c0 = max(0,      (int)floorf((bx0 - xr - XMIN) * INVH));
            int c1 = min(GW - 1, (int)floorf((bx1 + xr - XMIN) * INVH));
            int base = r * GW;
            range_sum(g_str, g_troff[base + c0], g_troff[base + c1 + 1],
                      qx, qy, qc, t0, t1, t2, t3);
            range_sum(g_ste, g_teoff[base + c0], g_teoff[base + c1 + 1],
                      qx, qy, qc, e0, e1, e2, e3);
            range_sum(g_sbw, g_bwoff[base + c0], g_bwoff[base + c1 + 1],
                      qx, qy, qc, w0, w1, w2, w3);
        }

        sh_tr[warp][lane] = (t0 + t1) + (t2 + t3);
        sh_te[warp][lane] = (e0 + e1) + (e2 + e3);
        sh_w [warp][lane] = (w0 + w1) + (w2 + w3);
        __syncthreads();

        if (warp == 0) {
            float s_tr = (sh_tr[0][lane] + sh_tr[1][lane]) +
                         (sh_tr[2][lane] + sh_tr[3][lane]);
            float s_te = (sh_te[0][lane] + sh_te[1][lane]) +
                         (sh_te[2][lane] + sh_te[3][lane]);
            float s_w  = (sh_w[0][lane]  + sh_w[1][lane]) +
                         (sh_w[2][lane]  + sh_w[3][lane]);

            float cnt    = (float)g_cnt;
            float p_y    = cnt * (1.0f / 1024.0f);
            float kde_tr = s_tr / DEN_TR;
            float kde_te = s_te / DEN_TE;
            float kde_w  = s_w / (fmaxf(cnt, 1.0f) * KDEN_F);

            float tr_rate = (float)g_hist_tr[bin] / 20000.0f;
            float te_rate = (float)g_hist_te[bin] / 10000.0f;

            float l[NCLS];
            float lmax = -1e30f;
            #pragma unroll
            for (int k = 0; k < NCLS; k++) {
                l[k] = fmaf(qx, __ldg(W + k), fmaf(qy, __ldg(W + NCLS + k), __ldg(b + k)));
                lmax = fmaxf(lmax, l[k]);
            }
            float se = 0.0f;
            #pragma unroll
            for (int k = 0; k < NCLS; k++) se += ex2((l[k] - lmax) * L2E_F);
            float hat_s = 1.0f / se;

            float lo = bin_lo(bin), hi = bin_hi(bin);
            float idx = (hat_s >= lo && hat_s <= hi) ? 1.0f : 0.0f;

            float d_t = (te_rate > 0.0f) ? kde_te / te_rate : 0.0f;
            float d_s = (tr_rate > 0.0f) ? kde_tr / tr_rate : 0.0f;

            float p_hs = kde_w * p_y / (kde_tr + 1e-8f);
            p_hs = fminf(fmaxf(p_hs, 0.0f), 1.0f);

            if (act) g_contrib[bin * NQ + qi] = p_hs * (d_t - d_s) * idx;
        }
        __syncthreads();
    }
}

// ------------------------- K6: final ---------------------------------------
__global__ void ec_final_kernel(float* __restrict__ out) {
    __shared__ float red[1024];
    int t = threadIdx.x;
    float ec = 0.0f;
    for (int bin = 0; bin < NBINS; bin++) {
        float s = 0.0f;
        for (int i = t; i < NQ; i += 1024) s += g_contrib[bin * NQ + i];
        red[t] = s;
        __syncthreads();
        for (int d = 512; d > 0; d >>= 1) {
            if (t < d) red[t] += red[t + d];
            __syncthreads();
        }
        if (t == 0) {
            float integral = (red[0] / (float)NQ) * 100.0f;
            float te_rate  = (float)g_hist_te[bin] / 10000.0f;
            if (te_rate > 0.0f) ec += te_rate * fabsf(integral);
        }
        __syncthreads();
    }
    if (t == 0) out[0] = ec;
}

// ------------------------- launch ------------------------------------------
extern "C" void kernel_launch(void* const* d_in, const int* in_sizes, int n_in,
                              void* d_out, int out_size) {
    const float* batch_x = (const float*)d_in[0];
    const int*   by      = (const int*)  d_in[1];
    const int*   bp      = (const int*)  d_in[2];
    const float* trp     = (const float*)d_in[3];
    const float* tep     = (const float*)d_in[4];

    const float *train_x, *test_x, *W, *b, *mc;
    if (in_sizes[5] == NTR * 2) {
        train_x = (const float*)d_in[5];
        test_x  = (const float*)d_in[6];
        W       = (const float*)d_in[7];
        b       = (const float*)d_in[8];
        mc      = (const float*)d_in[9];
    } else {
        W       = (const float*)d_in[5];
        b       = (const float*)d_in[6];
        train_x = (const float*)d_in[7];
        test_x  = (const float*)d_in[8];
        mc      = (const float*)d_in[9];
    }

    ec_init_kernel<<<64, 1024>>>();

    int total = NQTOT + NTR + NTE + NBATCH;
    ec_count_kernel<<<(total + 255) / 256, 256>>>(mc, train_x, test_x, batch_x,
                                                  by, bp, trp, tep);
    ec_scan_kernel<<<1, 1024>>>();
    ec_scatter_kernel<<<(total + 255) / 256, 256>>>(mc, train_x, test_x, batch_x,
                                                    by, bp);
    ec_main_kernel<<<MAINBLK, THREADS>>>(W, b);
    ec_final_kernel<<<1, 1024>>>((float*)d_out);
}

// round 13
// speedup vs baseline: 3.4996x; 1.5847x over previous
#include <cuda_runtime.h>

// ---------------------------------------------------------------------------
// ECLoss, spatially pruned KDE (R=1.7; dropped kernel <= 1.1e-7).
// Queries hierarchically sorted (1.0 major / 0.25 minor cells); data
// grid-sorted row-major in 0.25 cells. Work item = (32-query chunk, row
// half); items scheduled heavy-first (radial order) via dynamic stealing.
// 4-warp blocks, 8 blocks/SM, 8-deep unrolled broadcast loads.
// Main kernel emits raw KDE sums; separate epilogue kernel per query.
// (Resubmission of the Round-7 design: Round-10 bench was an infra failure,
// the design was never measured.)
// ---------------------------------------------------------------------------

namespace {
constexpr int NTR    = 20000;
constexpr int NTE    = 10000;
constexpr int NBATCH = 1024;
constexpr int NQ     = 10000;
constexpr int NBINS  = 15;
constexpr int NCLS   = 10;
constexpr int NQTOT  = NBINS * NQ;          // 150000

constexpr int GW = 44, GH = 44;
constexpr int NCELLS = GW * GH;
constexpr int QCELLS = 1600;
constexpr int QBUCKETS = NBINS * QCELLS;

constexpr float XMIN = -5.5f;
constexpr float H    = 0.25f;
constexpr float INVH = 4.0f;
constexpr float RCUT = 1.7f;
constexpr float R2   = RCUT * RCUT;

constexpr int WPB     = 313;                // 32-query chunks per bin
constexpr int NCHUNK  = NBINS * WPB;        // 4695
constexpr int NITEM   = NCHUNK * 2;         // row-half items
constexpr int THREADS = 128;
constexpr int MAINBLK = 1184;               // 8 blocks/SM
constexpr int SBUCK   = 64;                 // radial schedule buckets

constexpr double BW_D   = 0.3;
constexpr double PI_D   = 3.14159265358979323846;
constexpr double L2E_D  = 1.4426950408889634073599246810019;
constexpr double KDEN_D = 2.0 * PI_D * BW_D * BW_D;

constexpr float C1 = (float)(L2E_D / (BW_D * BW_D));
constexpr float C2 = (float)(L2E_D / (2.0 * BW_D * BW_D));
constexpr float KDEN_F = (float)KDEN_D;
constexpr float DEN_TR = (float)((double)NTR * KDEN_D);
constexpr float DEN_TE = (float)((double)NTE * KDEN_D);
constexpr float L2E_F  = (float)L2E_D;
constexpr float BIN_STEP = 1.0f / 15.0f;
}

// ------------------------- device globals ----------------------------------
__device__ float4 g_str[NTR];
__device__ float4 g_ste[NTE];
__device__ float4 g_sbw[NBATCH];
__device__ float4 g_q[NQTOT];               // (qx, qy, qc, -)

__device__ int g_qcnt[QBUCKETS];
__device__ int g_qoff[QBUCKETS + 1];
__device__ int g_qcur[QBUCKETS];
__device__ int g_trcnt[NCELLS], g_troff[NCELLS + 1], g_trcur[NCELLS];
__device__ int g_tecnt[NCELLS], g_teoff[NCELLS + 1], g_tecur[NCELLS];
__device__ int g_bwcnt[NCELLS], g_bwoff[NCELLS + 1], g_bwcur[NCELLS];

__device__ int g_scnt[SBUCK], g_soff[SBUCK + 1], g_scur[SBUCK];
__device__ int g_sched[NCHUNK];

__device__ int    g_hist_tr[NBINS];
__device__ int    g_hist_te[NBINS];
__device__ int    g_cnt;
__device__ int    g_work;
__device__ float4 g_half[2 * NQTOT];        // raw sums per (half, query)
__device__ float  g_contrib[NQTOT];

// ------------------------- helpers -----------------------------------------
__device__ __forceinline__ float ex2(float x) {
    float r;
    asm("ex2.approx.ftz.f32 %0, %1;" : "=f"(r) : "f"(x));
    return r;
}
__device__ __forceinline__ float bin_lo(int k) { return (float)k * BIN_STEP; }
__device__ __forceinline__ float bin_hi(int k) {
    return (k == NBINS - 1) ? 1.0f : (float)(k + 1) * BIN_STEP;
}
__device__ __forceinline__ int cell_coord(float v) {
    int c = (int)floorf((v - XMIN) * INVH);
    return min(max(c, 0), GW - 1);
}
__device__ __forceinline__ int qkey(float x, float y) {
    int tx = min(max((int)floorf((x + 5.0f) * 4.0f), 0), 39);
    int ty = min(max((int)floorf((y + 5.0f) * 4.0f), 0), 39);
    int mx = tx >> 2, my = ty >> 2;
    int sx = tx & 3,  sy = ty & 3;
    return (my * 10 + mx) * 16 + (sy * 4 + sx);
}

// ------------------------- K1: init ----------------------------------------
__global__ void ec_init_kernel() {
    int i = blockIdx.x * blockDim.x + threadIdx.x;
    int stride = gridDim.x * blockDim.x;
    for (int k = i; k < QBUCKETS; k += stride) g_qcnt[k] = 0;
    for (int k = i; k < NCELLS; k += stride) {
        g_trcnt[k] = 0; g_tecnt[k] = 0; g_bwcnt[k] = 0;
    }
    if (i < SBUCK) g_scnt[i] = 0;
    if (i < NBINS) { g_hist_tr[i] = 0; g_hist_te[i] = 0; }
    if (i == 0) { g_cnt = 0; g_work = 0; }
}

// ------------------------- K2: count ---------------------------------------
__global__ void ec_count_kernel(const float* __restrict__ mc,
                                const float* __restrict__ train_x,
                                const float* __restrict__ test_x,
                                const float* __restrict__ batch_x,
                                const int*   __restrict__ by,
                                const int*   __restrict__ bp,
                                const float* __restrict__ trp,
                                const float* __restrict__ tep) {
    int i = blockIdx.x * blockDim.x + threadIdx.x;
    if (i < NQTOT) {
        float qx = mc[2 * i], qy = mc[2 * i + 1];
        int bin = i / NQ;
        atomicAdd(&g_qcnt[bin * QCELLS + qkey(qx, qy)], 1);
        return;
    }
    int j = i - NQTOT;
    if (j < NTR) {
        float x = train_x[2 * j], y = train_x[2 * j + 1];
        atomicAdd(&g_trcnt[cell_coord(y) * GW + cell_coord(x)], 1);
        float p = trp[j];
        #pragma unroll
        for (int k = 0; k < NBINS; k++)
            if (p > bin_lo(k) && p <= bin_hi(k)) { atomicAdd(&g_hist_tr[k], 1); break; }
        return;
    }
    j -= NTR;
    if (j < NTE) {
        float x = test_x[2 * j], y = test_x[2 * j + 1];
        atomicAdd(&g_tecnt[cell_coord(y) * GW + cell_coord(x)], 1);
        float p = tep[j];
        #pragma unroll
        for (int k = 0; k < NBINS; k++)
            if (p > bin_lo(k) && p <= bin_hi(k)) { atomicAdd(&g_hist_te[k], 1); break; }
        return;
    }
    j -= NTE;
    if (j < NBATCH) {
        float x = batch_x[2 * j], y = batch_x[2 * j + 1];
        atomicAdd(&g_bwcnt[cell_coord(y) * GW + cell_coord(x)], 1);
        if (by[j] == bp[j]) atomicAdd(&g_cnt, 1);
    }
}

// ------------------------- K3: scans ---------------------------------------
__device__ void scan_excl(const int* cnt, int* off, int* cur, int n) {
    __shared__ int sh[1024];
    int t = threadIdx.x;
    int chunk = (n + 1023) / 1024;
    int lo = t * chunk, hi = min(lo + chunk, n);
    int s = 0;
    for (int i = lo; i < hi; i++) s += cnt[i];
    sh[t] = s;
    __syncthreads();
    for (int d = 1; d < 1024; d <<= 1) {
        int v = (t >= d) ? sh[t - d] : 0;
        __syncthreads();
        sh[t] += v;
        __syncthreads();
    }
    int excl = (t == 0) ? 0 : sh[t - 1];
    for (int i = lo; i < hi; i++) {
        off[i] = excl; cur[i] = excl;
        excl += cnt[i];
    }
    if (hi == n && lo <= n) off[n] = excl;
    __syncthreads();
}

__global__ void ec_scan_kernel() {
    scan_excl(g_qcnt,  g_qoff,  g_qcur,  QBUCKETS);
    scan_excl(g_trcnt, g_troff, g_trcur, NCELLS);
    scan_excl(g_tecnt, g_teoff, g_tecur, NCELLS);
    scan_excl(g_bwcnt, g_bwoff, g_bwcur, NCELLS);
}

// ------------------------- K4: scatter -------------------------------------
__global__ void ec_scatter_kernel(const float* __restrict__ mc,
                                  const float* __restrict__ train_x,
                                  const float* __restrict__ test_x,
                                  const float* __restrict__ batch_x,
                                  const int*   __restrict__ by,
                                  const int*   __restrict__ bp) {
    int i = blockIdx.x * blockDim.x + threadIdx.x;
    if (i < NQTOT) {
        float qx = mc[2 * i], qy = mc[2 * i + 1];
        int bin = i / NQ;
        int pos = atomicAdd(&g_qcur[bin * QCELLS + qkey(qx, qy)], 1);
        g_q[pos] = make_float4(qx, qy, -(qx * qx + qy * qy) * C2, 0.0f);
        return;
    }
    int j = i - NQTOT;
    if (j < NTR) {
        float x = train_x[2 * j], y = train_x[2 * j + 1];
        int pos = atomicAdd(&g_trcur[cell_coord(y) * GW + cell_coord(x)], 1);
        g_str[pos] = make_float4(x * C1, y * C1, -(x * x + y * y) * C2, 0.0f);
        return;
    }
    j -= NTR;
    if (j < NTE) {
        float x = test_x[2 * j], y = test_x[2 * j + 1];
        int pos = atomicAdd(&g_tecur[cell_coord(y) * GW + cell_coord(x)], 1);
        g_ste[pos] = make_float4(x * C1, y * C1, -(x * x + y * y) * C2, 0.0f);
        return;
    }
    j -= NTE;
    if (j < NBATCH) {
        float x = batch_x[2 * j], y = batch_x[2 * j + 1];
        bool c = (by[j] == bp[j]);
        int pos = atomicAdd(&g_bwcur[cell_coord(y) * GW + cell_coord(x)], 1);
        g_sbw[pos] = make_float4(x * C1, y * C1,
                                 c ? -(x * x + y * y) * C2 : -1e30f, 0.0f);
    }
}

// ------------------------- K5a/b/c: schedule (heavy chunks first) ----------
__device__ __forceinline__ int chunk_bucket(int c) {
    int bin = c / WPB;
    int lw  = c - bin * WPB;
    int slot = bin * NQ + min(lw * 32, NQ - 1);
    float4 qp = g_q[slot];
    float r2 = qp.x * qp.x + qp.y * qp.y;         // small r2 = dense = heavy
    return min(SBUCK - 1, (int)(r2 * ((float)SBUCK / 50.0f)));
}
__global__ void ec_sched_count() {
    int c = blockIdx.x * blockDim.x + threadIdx.x;
    if (c < NCHUNK) atomicAdd(&g_scnt[chunk_bucket(c)], 1);
}
__global__ void ec_sched_scan() {
    if (threadIdx.x == 0) {
        int acc = 0;
        for (int k = 0; k < SBUCK; k++) {
            g_soff[k] = acc; g_scur[k] = acc; acc += g_scnt[k];
        }
        g_soff[SBUCK] = acc;
    }
}
__global__ void ec_sched_scatter() {
    int c = blockIdx.x * blockDim.x + threadIdx.x;
    if (c < NCHUNK) {
        int pos = atomicAdd(&g_scur[chunk_bucket(c)], 1);
        g_sched[pos] = c;
    }
}

// ------------------------- K6: main ----------------------------------------
__device__ __forceinline__ void range_sum(const float4* __restrict__ d,
                                          int s, int e,
                                          float qx, float qy, float qc,
                                          float& a0, float& a1,
                                          float& a2, float& a3) {
    int i = s;
    for (; i + 8 <= e; i += 8) {
        float4 p0 = __ldg(d + i + 0);
        float4 p1 = __ldg(d + i + 1);
        float4 p2 = __ldg(d + i + 2);
        float4 p3 = __ldg(d + i + 3);
        float4 p4 = __ldg(d + i + 4);
        float4 p5 = __ldg(d + i + 5);
        float4 p6 = __ldg(d + i + 6);
        float4 p7 = __ldg(d + i + 7);
        a0 += ex2(fmaf(p0.x, qx, fmaf(p0.y, qy, p0.z) + qc));
        a1 += ex2(fmaf(p1.x, qx, fmaf(p1.y, qy, p1.z) + qc));
        a2 += ex2(fmaf(p2.x, qx, fmaf(p2.y, qy, p2.z) + qc));
        a3 += ex2(fmaf(p3.x, qx, fmaf(p3.y, qy, p3.z) + qc));
        a0 += ex2(fmaf(p4.x, qx, fmaf(p4.y, qy, p4.z) + qc));
        a1 += ex2(fmaf(p5.x, qx, fmaf(p5.y, qy, p5.z) + qc));
        a2 += ex2(fmaf(p6.x, qx, fmaf(p6.y, qy, p6.z) + qc));
        a3 += ex2(fmaf(p7.x, qx, fmaf(p7.y, qy, p7.z) + qc));
    }
    for (; i < e; i++) {
        float4 p = __ldg(d + i);
        a0 += ex2(fmaf(p.x, qx, fmaf(p.y, qy, p.z) + qc));
    }
}

__global__ void __launch_bounds__(THREADS, 8)
ec_main_kernel() {
    __shared__ float sh_tr[4][32], sh_te[4][32], sh_w[4][32];
    __shared__ int   sh_item;

    const int warp = threadIdx.x >> 5;
    const int lane = threadIdx.x & 31;
    const unsigned FULL = 0xffffffffu;

    while (true) {
        if (threadIdx.x == 0) sh_item = atomicAdd(&g_work, 1);
        __syncthreads();
        int item = sh_item;
        if (item >= NITEM) break;

        int c = g_sched[item >> 1];
        int h = item & 1;

        int bin = c / WPB;
        int lw  = c - bin * WPB;
        int qi  = lw * 32 + lane;
        bool act = (qi < NQ);
        int slot = bin * NQ + (act ? qi : NQ - 1);

        float4 qp = g_q[slot];
        float qx = qp.x, qy = qp.y, qc = qp.z;

        float bx0 = qx, bx1 = qx, by0 = qy, by1 = qy;
        #pragma unroll
        for (int o = 16; o; o >>= 1) {
            bx0 = fminf(bx0, __shfl_xor_sync(FULL, bx0, o));
            bx1 = fmaxf(bx1, __shfl_xor_sync(FULL, bx1, o));
            by0 = fminf(by0, __shfl_xor_sync(FULL, by0, o));
            by1 = fmaxf(by1, __shfl_xor_sync(FULL, by1, o));
        }

        int r0 = max(0,      (int)floorf((by0 - RCUT - XMIN) * INVH));
        int r1 = min(GH - 1, (int)floorf((by1 + RCUT - XMIN) * INVH));

        float t0 = 0.f, t1 = 0.f, t2 = 0.f, t3 = 0.f;
        float e0 = 0.f, e1 = 0.f, e2 = 0.f, e3 = 0.f;
        float w0 = 0.f, w1 = 0.f, w2 = 0.f, w3 = 0.f;

        // half h takes rows r0 + h*4 + warp, stride 8
        for (int r = r0 + h * 4 + warp; r <= r1; r += 8) {
            float rl = XMIN + (float)r * H;
            float rh = rl + H;
            float dy = fmaxf(fmaxf(by0 - rh, rl - by1), 0.0f);
            float rem = R2 - dy * dy;
            if (rem <= 0.0f) continue;
            float xr = sqrtf(rem);
            int c0 = max(0,      (int)floorf((bx0 - xr - XMIN) * INVH));
            int c1 = min(GW - 1, (int)floorf((bx1 + xr - XMIN) * INVH));
            int base = r * GW;
            range_sum(g_str, g_troff[base + c0], g_troff[base + c1 + 1],
                      qx, qy, qc, t0, t1, t2, t3);
            range_sum(g_ste, g_teoff[base + c0], g_teoff[base + c1 + 1],
                      qx, qy, qc, e0, e1, e2, e3);
            range_sum(g_sbw, g_bwoff[base + c0], g_bwoff[base + c1 + 1],
                      qx, qy, qc, w0, w1, w2, w3);
        }

        sh_tr[warp][lane] = (t0 + t1) + (t2 + t3);
        sh_te[warp][lane] = (e0 + e1) + (e2 + e3);
        sh_w [warp][lane] = (w0 + w1) + (w2 + w3);
        __syncthreads();

        if (warp == 0 && act) {
            float s_tr = (sh_tr[0][lane] + sh_tr[1][lane]) +
                         (sh_tr[2][lane] + sh_tr[3][lane]);
            float s_te = (sh_te[0][lane] + sh_te[1][lane]) +
                         (sh_te[2][lane] + sh_te[3][lane]);
            float s_w  = (sh_w[0][lane]  + sh_w[1][lane]) +
                         (sh_w[2][lane]  + sh_w[3][lane]);
            g_half[h * NQTOT + bin * NQ + qi] = make_float4(s_tr, s_te, s_w, 0.0f);
        }
        __syncthreads();
    }
}

// ------------------------- K7: epilogue per query --------------------------
__global__ void ec_epi_kernel(const float* __restrict__ W,
                              const float* __restrict__ b) {
    int i = blockIdx.x * blockDim.x + threadIdx.x;
    if (i >= NQTOT) return;
    int bin = i / NQ;

    float4 ha = g_half[i];
    float4 hb = g_half[NQTOT + i];
    float s_tr = ha.x + hb.x;
    float s_te = ha.y + hb.y;
    float s_w  = ha.z + hb.z;

    float4 qp = g_q[i];
    float qx = qp.x, qy = qp.y;

    float cnt    = (float)g_cnt;
    float p_y    = cnt * (1.0f / 1024.0f);
    float kde_tr = s_tr / DEN_TR;
    float kde_te = s_te / DEN_TE;
    float kde_w  = s_w / (fmaxf(cnt, 1.0f) * KDEN_F);

    float tr_rate = (float)g_hist_tr[bin] / 20000.0f;
    float te_rate = (float)g_hist_te[bin] / 10000.0f;

    float l[NCLS];
    float lmax = -1e30f;
    #pragma unroll
    for (int k = 0; k < NCLS; k++) {
        l[k] = fmaf(qx, __ldg(W + k), fmaf(qy, __ldg(W + NCLS + k), __ldg(b + k)));
        lmax = fmaxf(lmax, l[k]);
    }
    float se = 0.0f;
    #pragma unroll
    for (int k = 0; k < NCLS; k++) se += ex2((l[k] - lmax) * L2E_F);
    float hat_s = 1.0f / se;

    float lo = bin_lo(bin), hi = bin_hi(bin);
    float idx = (hat_s >= lo && hat_s <= hi) ? 1.0f : 0.0f;

    float d_t = (te_rate > 0.0f) ? kde_te / te_rate : 0.0f;
    float d_s = (tr_rate > 0.0f) ? kde_tr / tr_rate : 0.0f;

    float p_hs = kde_w * p_y / (kde_tr + 1e-8f);
    p_hs = fminf(fmaxf(p_hs, 0.0f), 1.0f);

    g_contrib[i] = p_hs * (d_t - d_s) * idx;
}

// ------------------------- K8: final ---------------------------------------
__global__ void ec_final_kernel(float* __restrict__ out) {
    __shared__ float red[1024];
    int t = threadIdx.x;
    float ec = 0.0f;
    for (int bin = 0; bin < NBINS; bin++) {
        float s = 0.0f;
        for (int i = t; i < NQ; i += 1024) s += g_contrib[bin * NQ + i];
        red[t] = s;
        __syncthreads();
        for (int d = 512; d > 0; d >>= 1) {
            if (t < d) red[t] += red[t + d];
            __syncthreads();
        }
        if (t == 0) {
            float integral = (red[0] / (float)NQ) * 100.0f;
            float te_rate  = (float)g_hist_te[bin] / 10000.0f;
            if (te_rate > 0.0f) ec += te_rate * fabsf(integral);
        }
        __syncthreads();
    }
    if (t == 0) out[0] = ec;
}

// ------------------------- launch ------------------------------------------
extern "C" void kernel_launch(void* const* d_in, const int* in_sizes, int n_in,
                              void* d_out, int out_size) {
    const float* batch_x = (const float*)d_in[0];
    const int*   by      = (const int*)  d_in[1];
    const int*   bp      = (const int*)  d_in[2];
    const float* trp     = (const float*)d_in[3];
    const float* tep     = (const float*)d_in[4];

    const float *train_x, *test_x, *W, *b, *mc;
    if (in_sizes[5] == NTR * 2) {
        train_x = (const float*)d_in[5];
        test_x  = (const float*)d_in[6];
        W       = (const float*)d_in[7];
        b       = (const float*)d_in[8];
        mc      = (const float*)d_in[9];
    } else {
        W       = (const float*)d_in[5];
        b       = (const float*)d_in[6];
        train_x = (const float*)d_in[7];
        test_x  = (const float*)d_in[8];
        mc      = (const float*)d_in[9];
    }

    ec_init_kernel<<<64, 1024>>>();

    int total = NQTOT + NTR + NTE + NBATCH;
    ec_count_kernel<<<(total + 255) / 256, 256>>>(mc, train_x, test_x, batch_x,
                                                  by, bp, trp, tep);
    ec_scan_kernel<<<1, 1024>>>();
    ec_scatter_kernel<<<(total + 255) / 256, 256>>>(mc, train_x, test_x, batch_x,
                                                    by, bp);
    ec_sched_count<<<(NCHUNK + 255) / 256, 256>>>();
    ec_sched_scan<<<1, 32>>>();
    ec_sched_scatter<<<(NCHUNK + 255) / 256, 256>>>();

    ec_main_kernel<<<MAINBLK, THREADS>>>();
    ec_epi_kernel<<<(NQTOT + 255) / 256, 256>>>(W, b);
    ec_final_kernel<<<1, 1024>>>((float*)d_out);
}